// round 4
// baseline (speedup 1.0000x reference)
#include <cuda_runtime.h>
#include <math_constants.h>

#define NN 50000
#define EE 800000
#define DIN 18
#define HH 128
#define NEG_SLOPE 0.2f
#define BN_EPS 1e-5f

// ---------------- scratch (no allocation allowed) ----------------
__device__ int   g_deg[NN];
__device__ int   g_fill[NN];
__device__ int   g_rowptr[NN + 1];
__device__ int   g_cols[EE];
__device__ float g_nmean[NN * DIN];
__device__ float g_h[NN * HH];
__device__ float g_hval[NN * HH];
__device__ float g_ssrc[NN * 4];
__device__ float g_sdst[NN * 4];
__device__ float g_wpack[HH * HH];

__device__ __forceinline__ float leaky_f(float v) { return v >= 0.f ? v : NEG_SLOPE * v; }

// ---------------- CSR build ----------------
__global__ void k_zero() {
    int i = blockIdx.x * blockDim.x + threadIdx.x;
    if (i < NN) { g_deg[i] = 0; g_fill[i] = 0; }
}

__global__ void k_count(const int* __restrict__ ei) {
    int e = blockIdx.x * blockDim.x + threadIdx.x;
    if (e < EE) atomicAdd(&g_deg[ei[e]], 1);
}

__global__ void k_scan() {
    __shared__ int wsum[32];
    __shared__ int carry;
    int tid = threadIdx.x;
    int lane = tid & 31, wid = tid >> 5;
    if (tid == 0) { carry = 0; g_rowptr[0] = 0; }
    __syncthreads();
    for (int base = 0; base < NN; base += 1024) {
        int idx = base + tid;
        int v = (idx < NN) ? g_deg[idx] : 0;
        int x = v;
        #pragma unroll
        for (int o = 1; o < 32; o <<= 1) {
            int y = __shfl_up_sync(0xffffffffu, x, o);
            if (lane >= o) x += y;
        }
        if (lane == 31) wsum[wid] = x;
        __syncthreads();
        if (wid == 0) {
            int s = wsum[lane];
            #pragma unroll
            for (int o = 1; o < 32; o <<= 1) {
                int y = __shfl_up_sync(0xffffffffu, s, o);
                if (lane >= o) s += y;
            }
            wsum[lane] = s;
        }
        __syncthreads();
        int incl = x + (wid ? wsum[wid - 1] : 0) + carry;
        if (idx < NN) g_rowptr[idx + 1] = incl;
        __syncthreads();
        if (tid == 1023) carry = incl;
        __syncthreads();
    }
}

__global__ void k_scatter(const int* __restrict__ ei) {
    int e = blockIdx.x * blockDim.x + threadIdx.x;
    if (e < EE) {
        int r = ei[e];
        int pos = g_rowptr[r] + atomicAdd(&g_fill[r], 1);
        g_cols[pos] = ei[EE + e];
    }
}

// ---------------- neighbor mean (warp per node) ----------------
__global__ void k_nmean(const float* __restrict__ x) {
    int w = (blockIdx.x * blockDim.x + threadIdx.x) >> 5;
    int lane = threadIdx.x & 31;
    if (w >= NN) return;
    int s0 = g_rowptr[w], e0 = g_rowptr[w + 1];
    float acc = 0.f;
    for (int j = s0; j < e0; j++) {
        int c = __ldg(&g_cols[j]);
        if (lane < DIN) acc += __ldg(&x[c * DIN + lane]);
    }
    float inv = 1.f / ((float)(e0 - s0) + 1e-8f);
    if (lane < DIN) g_nmean[w * DIN + lane] = acc * inv;
}

// ---------------- input transform: h = x@Win + bin + nmean@Wagg + bagg ----------------
__global__ void k_input(const float* __restrict__ x, const float* __restrict__ Win,
                        const float* __restrict__ bin, const float* __restrict__ Wagg,
                        const float* __restrict__ bagg) {
    __shared__ float xs[32][DIN];
    __shared__ float ns[32][DIN];
    int f = threadIdx.x;   // 128
    int n0 = blockIdx.x * 32;
    for (int t = f; t < 32 * DIN; t += 128) {
        int m = t / DIN, k = t % DIN;
        int gn = n0 + m;
        xs[m][k] = (gn < NN) ? x[gn * DIN + k] : 0.f;
        ns[m][k] = (gn < NN) ? g_nmean[gn * DIN + k] : 0.f;
    }
    float wi[DIN], wa[DIN];
    #pragma unroll
    for (int k = 0; k < DIN; k++) { wi[k] = Win[k * HH + f]; wa[k] = Wagg[k * HH + f]; }
    float bias = bin[f] + bagg[f];
    __syncthreads();
    for (int m = 0; m < 32; m++) {
        int gn = n0 + m;
        if (gn >= NN) break;
        float acc = bias;
        #pragma unroll
        for (int k = 0; k < DIN; k++) acc += xs[m][k] * wi[k] + ns[m][k] * wa[k];
        g_h[gn * HH + f] = acc;
    }
}

// ---------------- GEMM: g_hval = g_h @ W + bias (optionally leaky) ----------------
// use_pack != 0 -> weights come from the device-global g_wpack (NEVER pass a
// __device__ symbol from host: on GB300 ATS silently dereferences the host
// shadow array -> zeros).
__global__ void __launch_bounds__(256) k_gemm(const float* __restrict__ Warg,
                                              const float* __restrict__ bias,
                                              int act, int use_pack) {
    const float* __restrict__ W = use_pack ? g_wpack : Warg;
    __shared__ float As[64][33];
    __shared__ float Ws[32][128];
    int tid = threadIdx.x;
    int tx = tid & 31, ty = tid >> 5;
    int row0 = blockIdx.x * 64;
    float acc[8][4];
    #pragma unroll
    for (int i = 0; i < 8; i++)
        #pragma unroll
        for (int q = 0; q < 4; q++) acc[i][q] = 0.f;

    for (int k0 = 0; k0 < HH; k0 += 32) {
        int m = tid >> 2, kq = (tid & 3) * 8;
        int gr = row0 + m;
        float4 a0, a1;
        if (gr < NN) {
            a0 = *(const float4*)&g_h[gr * HH + k0 + kq];
            a1 = *(const float4*)&g_h[gr * HH + k0 + kq + 4];
        } else {
            a0 = make_float4(0, 0, 0, 0); a1 = a0;
        }
        As[m][kq + 0] = a0.x; As[m][kq + 1] = a0.y; As[m][kq + 2] = a0.z; As[m][kq + 3] = a0.w;
        As[m][kq + 4] = a1.x; As[m][kq + 5] = a1.y; As[m][kq + 6] = a1.z; As[m][kq + 7] = a1.w;
        #pragma unroll
        for (int i = 0; i < 4; i++) {
            int kk = ty + i * 8;
            *(float4*)&Ws[kk][tx * 4] = *(const float4*)&W[(k0 + kk) * HH + tx * 4];
        }
        __syncthreads();
        #pragma unroll
        for (int k = 0; k < 32; k++) {
            float4 b = *(const float4*)&Ws[k][tx * 4];
            #pragma unroll
            for (int i = 0; i < 8; i++) {
                float a = As[ty * 8 + i][k];
                acc[i][0] += a * b.x; acc[i][1] += a * b.y;
                acc[i][2] += a * b.z; acc[i][3] += a * b.w;
            }
        }
        __syncthreads();
    }
    float4 bb = *(const float4*)&bias[tx * 4];
    #pragma unroll
    for (int i = 0; i < 8; i++) {
        int gr = row0 + ty * 8 + i;
        if (gr < NN) {
            float4 v;
            v.x = acc[i][0] + bb.x; v.y = acc[i][1] + bb.y;
            v.z = acc[i][2] + bb.z; v.w = acc[i][3] + bb.w;
            if (act) { v.x = leaky_f(v.x); v.y = leaky_f(v.y); v.z = leaky_f(v.z); v.w = leaky_f(v.w); }
            *(float4*)&g_hval[gr * HH + tx * 4] = v;
        }
    }
}

// ---------------- attention scores ----------------
__global__ void k_scores1(const float* __restrict__ asrc, const float* __restrict__ adst) {
    int w = (blockIdx.x * blockDim.x + threadIdx.x) >> 5;
    int lane = threadIdx.x & 31;
    if (w >= NN) return;
    float a = 0.f, b = 0.f;
    #pragma unroll
    for (int q = 0; q < 4; q++) {
        int f = lane + q * 32;
        float hv = g_h[w * HH + f];
        a += hv * asrc[f];
        b += hv * adst[f];
    }
    #pragma unroll
    for (int o = 16; o; o >>= 1) {
        a += __shfl_xor_sync(0xffffffffu, a, o);
        b += __shfl_xor_sync(0xffffffffu, b, o);
    }
    if (lane == 0) { g_ssrc[w] = a; g_sdst[w] = b; }
}

__global__ void k_scores4(const float* __restrict__ asrc, const float* __restrict__ adst) {
    int w = (blockIdx.x * blockDim.x + threadIdx.x) >> 5;
    int lane = threadIdx.x & 31;
    if (w >= NN) return;
    float as[4] = {0, 0, 0, 0}, ad[4] = {0, 0, 0, 0};
    #pragma unroll
    for (int q = 0; q < 4; q++) {
        int f = lane + q * 32;
        float hv = g_h[w * HH + f];
        #pragma unroll
        for (int h = 0; h < 4; h++) {
            as[h] += hv * asrc[h * HH + f];
            ad[h] += hv * adst[h * HH + f];
        }
    }
    #pragma unroll
    for (int h = 0; h < 4; h++) {
        #pragma unroll
        for (int o = 16; o; o >>= 1) {
            as[h] += __shfl_xor_sync(0xffffffffu, as[h], o);
            ad[h] += __shfl_xor_sync(0xffffffffu, ad[h], o);
        }
    }
    if (lane == 0) {
        #pragma unroll
        for (int h = 0; h < 4; h++) { g_ssrc[w * 4 + h] = as[h]; g_sdst[w * 4 + h] = ad[h]; }
    }
}

// ---------------- attention aggregate + BN + residual + leaky (in-place on g_h) ----------------
__global__ void __launch_bounds__(256) k_attn(const float* __restrict__ bn_g,
                                              const float* __restrict__ bn_b,
                                              const float* __restrict__ bn_m,
                                              const float* __restrict__ bn_v,
                                              int residual, int multi) {
    int w = (blockIdx.x * blockDim.x + threadIdx.x) >> 5;
    int lane = threadIdx.x & 31;
    if (w >= NN) return;
    int s0 = g_rowptr[w], e0 = g_rowptr[w + 1];
    int hd = multi ? (lane >> 3) : 0;
    float si = multi ? g_ssrc[w * 4 + hd] : g_ssrc[w];

    // per-lane BN params (4 consecutive features per lane), hoisted
    int f0 = lane * 4;
    float4 bnm4 = *(const float4*)&bn_m[f0];
    float4 bnv4 = *(const float4*)&bn_v[f0];
    float4 bng4 = *(const float4*)&bn_g[f0];
    float4 bnb4 = *(const float4*)&bn_b[f0];
    float sc0 = bng4.x * rsqrtf(bnv4.x + BN_EPS);
    float sc1 = bng4.y * rsqrtf(bnv4.y + BN_EPS);
    float sc2 = bng4.z * rsqrtf(bnv4.z + BN_EPS);
    float sc3 = bng4.w * rsqrtf(bnv4.w + BN_EPS);

    float4 acc = make_float4(0, 0, 0, 0);
    float m = -CUDART_INF_F, s = 0.f;
    const float4* hv4 = (const float4*)g_hval;
    for (int j = s0; j < e0; j++) {
        int c = __ldg(&g_cols[j]);
        float sd = multi ? __ldg(&g_sdst[c * 4 + hd]) : __ldg(&g_sdst[c]);
        float e = leaky_f(si + sd);
        float wgt;
        if (e <= m) {
            wgt = __expf(e - m);
        } else {
            float sc = __expf(m - e);   // exp(-inf)=0 on first edge
            s *= sc;
            acc.x *= sc; acc.y *= sc; acc.z *= sc; acc.w *= sc;
            m = e;
            wgt = 1.f;
        }
        s += wgt;
        float4 hv = __ldg(&hv4[c * 32 + lane]);
        acc.x += wgt * hv.x; acc.y += wgt * hv.y;
        acc.z += wgt * hv.z; acc.w += wgt * hv.w;
    }
    float inv = 1.f / (s + 1e-16f);
    float o0 = (acc.x * inv - bnm4.x) * sc0 + bnb4.x;
    float o1 = (acc.y * inv - bnm4.y) * sc1 + bnb4.y;
    float o2 = (acc.z * inv - bnm4.z) * sc2 + bnb4.z;
    float o3 = (acc.w * inv - bnm4.w) * sc3 + bnb4.w;
    if (residual) {
        float4 r4 = *(const float4*)&g_h[w * HH + f0];
        o0 += r4.x; o1 += r4.y; o2 += r4.z; o3 += r4.w;
    }
    *(float4*)&g_h[w * HH + f0] =
        make_float4(leaky_f(o0), leaky_f(o1), leaky_f(o2), leaky_f(o3));
}

// ---------------- pack multi-head weight [4,128,32] -> [128,128] head-major cols ----------------
__global__ void k_pack(const float* __restrict__ mhWv) {
    int t = blockIdx.x * blockDim.x + threadIdx.x;
    if (t < HH * HH) {
        int k = t >> 7, f = t & 127;
        int h = f >> 5, e = f & 31;
        g_wpack[t] = mhWv[(h * HH + k) * 32 + e];
    }
}

// ---------------- output head: out = x[:,15:18] + (g_hval @ W_o2 + b_o2) ----------------
__global__ void k_out(const float* __restrict__ x, const float* __restrict__ Wo2,
                      const float* __restrict__ bo2, float* __restrict__ out) {
    int w = (blockIdx.x * blockDim.x + threadIdx.x) >> 5;
    int lane = threadIdx.x & 31;
    if (w >= NN) return;
    float a0 = 0.f, a1 = 0.f, a2 = 0.f;
    #pragma unroll
    for (int q = 0; q < 4; q++) {
        int f = lane + q * 32;
        float t = g_hval[w * HH + f];
        a0 += t * Wo2[f * 3 + 0];
        a1 += t * Wo2[f * 3 + 1];
        a2 += t * Wo2[f * 3 + 2];
    }
    #pragma unroll
    for (int o = 16; o; o >>= 1) {
        a0 += __shfl_xor_sync(0xffffffffu, a0, o);
        a1 += __shfl_xor_sync(0xffffffffu, a1, o);
        a2 += __shfl_xor_sync(0xffffffffu, a2, o);
    }
    if (lane < 3) {
        float a = (lane == 0) ? a0 : (lane == 1) ? a1 : a2;
        out[w * 3 + lane] = x[w * DIN + 15 + lane] + a + bo2[lane];
    }
}

// ---------------- launch ----------------
extern "C" void kernel_launch(void* const* d_in, const int* in_sizes, int n_in,
                              void* d_out, int out_size) {
    const float* x     = (const float*)d_in[0];
    const int*   ei    = (const int*)d_in[1];
    const float* Win   = (const float*)d_in[2];
    const float* bin   = (const float*)d_in[3];
    const float* Wagg  = (const float*)d_in[4];
    const float* bagg  = (const float*)d_in[5];
    const float* shWv  = (const float*)d_in[6];
    const float* shb   = (const float*)d_in[7];
    const float* shas  = (const float*)d_in[8];
    const float* shad  = (const float*)d_in[9];
    const float* mhWv  = (const float*)d_in[10];
    const float* mhb   = (const float*)d_in[11];
    const float* mhas  = (const float*)d_in[12];
    const float* mhad  = (const float*)d_in[13];
    const float* bng   = (const float*)d_in[14];
    const float* bnb   = (const float*)d_in[15];
    const float* bnm   = (const float*)d_in[16];
    const float* bnv   = (const float*)d_in[17];
    const float* Wo1   = (const float*)d_in[18];
    const float* bo1   = (const float*)d_in[19];
    const float* Wo2   = (const float*)d_in[20];
    const float* bo2   = (const float*)d_in[21];
    float* out = (float*)d_out;

    const int WPB = 8;                       // warps per block for warp-per-node kernels
    dim3 nwarp_grid((NN + WPB - 1) / WPB);
    dim3 gemm_grid((NN + 63) / 64);

    // CSR build
    k_zero<<<(NN + 255) / 256, 256>>>();
    k_count<<<(EE + 255) / 256, 256>>>(ei);
    k_scan<<<1, 1024>>>();
    k_scatter<<<(EE + 255) / 256, 256>>>(ei);
    k_pack<<<(HH * HH + 255) / 256, 256>>>(mhWv);

    // input transform
    k_nmean<<<nwarp_grid, WPB * 32>>>(x);
    k_input<<<(NN + 31) / 32, 128>>>(x, Win, bin, Wagg, bagg);

    // layer 0: single-head, BN[0], residual
    k_gemm<<<gemm_grid, 256>>>(shWv, shb, 0, 0);
    k_scores1<<<nwarp_grid, WPB * 32>>>(shas, shad);
    k_attn<<<nwarp_grid, WPB * 32>>>(bng, bnb, bnm, bnv, 1, 0);

    // layer 1: multi-head, BN[1], no residual  (weights from g_wpack, device-side)
    k_gemm<<<gemm_grid, 256>>>(nullptr, mhb, 0, 1);
    k_scores4<<<nwarp_grid, WPB * 32>>>(mhas, mhad);
    k_attn<<<nwarp_grid, WPB * 32>>>(bng + HH, bnb + HH, bnm + HH, bnv + HH, 0, 1);

    // layer 2: single-head (set 1), BN[2], residual
    k_gemm<<<gemm_grid, 256>>>(shWv + HH * HH, shb + HH, 0, 0);
    k_scores1<<<nwarp_grid, WPB * 32>>>(shas + HH, shad + HH);
    k_attn<<<nwarp_grid, WPB * 32>>>(bng + 2 * HH, bnb + 2 * HH, bnm + 2 * HH, bnv + 2 * HH, 1, 0);

    // output head
    k_gemm<<<gemm_grid, 256>>>(Wo1, bo1, 1, 0);
    k_out<<<nwarp_grid, WPB * 32>>>(x, Wo2, bo2, out);
}

// round 7
// speedup vs baseline: 1.2547x; 1.2547x over previous
#include <cuda_runtime.h>
#include <cuda_bf16.h>
#include <math_constants.h>
#include <cstdint>

#define NN 50000
#define EE 800000
#define DIN 18
#define HH 128
#define NEG_SLOPE 0.2f
#define BN_EPS 1e-5f

// ---------------- scratch (no allocation allowed) ----------------
__device__ int   g_deg[NN];
__device__ int   g_fill[NN];
__device__ int   g_rowptr[NN + 1];
__device__ int   g_cols[EE];
__device__ float g_nmean[NN * DIN];
__device__ float g_h[NN * HH];
__device__ float g_hval[NN * HH];
__device__ float g_ssrc[NN * 4];
__device__ float g_sdst[NN * 4];
__device__ __nv_bfloat16 g_wtb[4][HH * HH];   // bf16 weights, [N][K] (col-major B)

__device__ __forceinline__ float leaky_f(float v) { return v >= 0.f ? v : NEG_SLOPE * v; }

// ---------------- CSR build ----------------
__global__ void k_zero() {
    int i = blockIdx.x * blockDim.x + threadIdx.x;
    if (i < NN) { g_deg[i] = 0; g_fill[i] = 0; }
}

__global__ void k_count(const int* __restrict__ ei) {
    int e = blockIdx.x * blockDim.x + threadIdx.x;
    if (e < EE) atomicAdd(&g_deg[ei[e]], 1);
}

__global__ void k_scan() {
    __shared__ int wsum[32];
    __shared__ int carry;
    int tid = threadIdx.x;
    int lane = tid & 31, wid = tid >> 5;
    if (tid == 0) { carry = 0; g_rowptr[0] = 0; }
    __syncthreads();
    for (int base = 0; base < NN; base += 1024) {
        int idx = base + tid;
        int v = (idx < NN) ? g_deg[idx] : 0;
        int x = v;
        #pragma unroll
        for (int o = 1; o < 32; o <<= 1) {
            int y = __shfl_up_sync(0xffffffffu, x, o);
            if (lane >= o) x += y;
        }
        if (lane == 31) wsum[wid] = x;
        __syncthreads();
        if (wid == 0) {
            int s = wsum[lane];
            #pragma unroll
            for (int o = 1; o < 32; o <<= 1) {
                int y = __shfl_up_sync(0xffffffffu, s, o);
                if (lane >= o) s += y;
            }
            wsum[lane] = s;
        }
        __syncthreads();
        int incl = x + (wid ? wsum[wid - 1] : 0) + carry;
        if (idx < NN) g_rowptr[idx + 1] = incl;
        __syncthreads();
        if (tid == 1023) carry = incl;
        __syncthreads();
    }
}

__global__ void k_scatter(const int* __restrict__ ei) {
    int e = blockIdx.x * blockDim.x + threadIdx.x;
    if (e < EE) {
        int r = ei[e];
        int pos = g_rowptr[r] + atomicAdd(&g_fill[r], 1);
        g_cols[pos] = ei[EE + e];
    }
}

// ---------------- neighbor mean (warp per node) ----------------
__global__ void k_nmean(const float* __restrict__ x) {
    int w = (blockIdx.x * blockDim.x + threadIdx.x) >> 5;
    int lane = threadIdx.x & 31;
    if (w >= NN) return;
    int s0 = g_rowptr[w], e0 = g_rowptr[w + 1];
    float acc = 0.f;
    for (int j = s0; j < e0; j++) {
        int c = __ldg(&g_cols[j]);
        if (lane < DIN) acc += __ldg(&x[c * DIN + lane]);
    }
    float inv = 1.f / ((float)(e0 - s0) + 1e-8f);
    if (lane < DIN) g_nmean[w * DIN + lane] = acc * inv;
}

// ---------------- input transform ----------------
__global__ void k_input(const float* __restrict__ x, const float* __restrict__ Win,
                        const float* __restrict__ bin, const float* __restrict__ Wagg,
                        const float* __restrict__ bagg) {
    __shared__ float xs[32][DIN];
    __shared__ float ns[32][DIN];
    int f = threadIdx.x;   // 128
    int n0 = blockIdx.x * 32;
    for (int t = f; t < 32 * DIN; t += 128) {
        int m = t / DIN, k = t % DIN;
        int gn = n0 + m;
        xs[m][k] = (gn < NN) ? x[gn * DIN + k] : 0.f;
        ns[m][k] = (gn < NN) ? g_nmean[gn * DIN + k] : 0.f;
    }
    float wi[DIN], wa[DIN];
    #pragma unroll
    for (int k = 0; k < DIN; k++) { wi[k] = Win[k * HH + f]; wa[k] = Wagg[k * HH + f]; }
    float bias = bin[f] + bagg[f];
    __syncthreads();
    for (int m = 0; m < 32; m++) {
        int gn = n0 + m;
        if (gn >= NN) break;
        float acc = bias;
        #pragma unroll
        for (int k = 0; k < DIN; k++) acc += xs[m][k] * wi[k] + ns[m][k] * wa[k];
        g_h[gn * HH + f] = acc;
    }
}

// ---------------- weight pre-pass: bf16, transposed to [N][K] ----------------
// buf 0: sh_Wv[0]; buf 1: packed multihead (mh_Wv [4,128,32] -> cols head-major);
// buf 2: sh_Wv[1]; buf 3: W_o1.  All referenced device-side only.
__global__ void k_wt(const float* __restrict__ shWv, const float* __restrict__ mhWv,
                     const float* __restrict__ Wo1) {
    int t = blockIdx.x * blockDim.x + threadIdx.x;     // 4 * 16384
    int buf = t >> 14;
    int r = t & 16383;
    int n = r >> 7, k = r & 127;
    float v;
    if (buf == 1) {
        int h = n >> 5, e = n & 31;
        v = mhWv[(h * HH + k) * 32 + e];
    } else if (buf == 0) {
        v = shWv[k * HH + n];
    } else if (buf == 2) {
        v = shWv[HH * HH + k * HH + n];
    } else {
        v = Wo1[k * HH + n];
    }
    g_wtb[buf][n * HH + k] = __float2bfloat16(v);
}

// ---------------- mma.sync GEMM: g_hval = g_h @ W + bias (optional leaky) ----------------
// CTA: 128 rows x 128 cols, 256 threads (8 warps, 2 along M x 4 along N).
// Warp tile 64x32 = 4x4 m16n8k16 bf16 MMAs per K-step; K=128 in 8 steps.
// smem: As [128][136] bf16 (row stride 136 halves = 272B, uint4-aligned, conflict-free),
//       Bs [128][136] bf16 holding Wt[n][k].
#define GM_STRIDE 136
#define GM_SM_B 34816
#define GM_SM_TOTAL 69632

#define MMA16816(c, a, b) \
    asm volatile("mma.sync.aligned.m16n8k16.row.col.f32.bf16.bf16.f32 " \
        "{%0,%1,%2,%3}, {%4,%5,%6,%7}, {%8,%9}, {%0,%1,%2,%3};" \
        : "+f"((c)[0]), "+f"((c)[1]), "+f"((c)[2]), "+f"((c)[3]) \
        : "r"((a)[0]), "r"((a)[1]), "r"((a)[2]), "r"((a)[3]), \
          "r"((b)[0]), "r"((b)[1]))

__global__ void __launch_bounds__(256) k_gemm_mma(int widx, const float* __restrict__ bias,
                                                  int act) {
    extern __shared__ __align__(16) char smem[];
    __nv_bfloat16* As = (__nv_bfloat16*)smem;
    __nv_bfloat16* Bs = (__nv_bfloat16*)(smem + GM_SM_B);
    int tid = threadIdx.x, lane = tid & 31, wid = tid >> 5;
    int row0 = blockIdx.x * 128;

    // ---- convert A rows fp32 -> bf16 (each thread: one row-half = 64 cols) ----
    {
        int r = tid >> 1, half = tid & 1;
        int gr = row0 + r;
        const float4* src = (const float4*)&g_h[(size_t)gr * HH + half * 64];
        __nv_bfloat16* dst = &As[r * GM_STRIDE + half * 64];
        #pragma unroll
        for (int q = 0; q < 8; q++) {
            float4 f0, f1;
            if (gr < NN) { f0 = src[q * 2]; f1 = src[q * 2 + 1]; }
            else { f0 = make_float4(0, 0, 0, 0); f1 = f0; }
            __nv_bfloat162 h0 = __floats2bfloat162_rn(f0.x, f0.y);
            __nv_bfloat162 h1 = __floats2bfloat162_rn(f0.z, f0.w);
            __nv_bfloat162 h2 = __floats2bfloat162_rn(f1.x, f1.y);
            __nv_bfloat162 h3 = __floats2bfloat162_rn(f1.z, f1.w);
            uint4 v;
            v.x = *(uint32_t*)&h0; v.y = *(uint32_t*)&h1;
            v.z = *(uint32_t*)&h2; v.w = *(uint32_t*)&h3;
            *(uint4*)(dst + q * 8) = v;
        }
    }
    // ---- copy Wt bf16 gmem -> smem (coalesced uint4) ----
    {
        const uint4* src = (const uint4*)g_wtb[widx];
        #pragma unroll
        for (int i = 0; i < 8; i++) {
            int idx = tid + i * 256;
            int n = idx >> 4, j = idx & 15;
            *(uint4*)&Bs[n * GM_STRIDE + j * 8] = src[n * 16 + j];
        }
    }
    __syncthreads();

    int mw = wid & 1, nw = wid >> 1;
    int m0 = mw * 64, n0 = nw * 32;
    int gid = lane >> 2, qd = (lane & 3) * 2;

    float acc[4][4][4];
    #pragma unroll
    for (int a = 0; a < 4; a++)
        #pragma unroll
        for (int b = 0; b < 4; b++)
            #pragma unroll
            for (int c = 0; c < 4; c++) acc[a][b][c] = 0.f;

    #pragma unroll
    for (int ks = 0; ks < 8; ks++) {
        int kc = ks * 16 + qd;
        uint32_t af[4][4], bf[4][2];
        #pragma unroll
        for (int ms = 0; ms < 4; ms++) {
            const __nv_bfloat16* p = &As[(m0 + ms * 16 + gid) * GM_STRIDE + kc];
            af[ms][0] = *(const uint32_t*)p;
            af[ms][1] = *(const uint32_t*)(p + 8 * GM_STRIDE);
            af[ms][2] = *(const uint32_t*)(p + 8);
            af[ms][3] = *(const uint32_t*)(p + 8 * GM_STRIDE + 8);
        }
        #pragma unroll
        for (int ns = 0; ns < 4; ns++) {
            const __nv_bfloat16* p = &Bs[(n0 + ns * 8 + gid) * GM_STRIDE + kc];
            bf[ns][0] = *(const uint32_t*)p;
            bf[ns][1] = *(const uint32_t*)(p + 8);
        }
        #pragma unroll
        for (int ms = 0; ms < 4; ms++)
            #pragma unroll
            for (int ns = 0; ns < 4; ns++)
                MMA16816(acc[ms][ns], af[ms], bf[ns]);
    }

    // ---- epilogue: bias (+leaky), float2 stores ----
    #pragma unroll
    for (int ms = 0; ms < 4; ms++) {
        int r1 = row0 + m0 + ms * 16 + gid;
        int r2 = r1 + 8;
        #pragma unroll
        for (int ns = 0; ns < 4; ns++) {
            int col = n0 + ns * 8 + qd;
            float2 b2 = *(const float2*)&bias[col];
            float v0 = acc[ms][ns][0] + b2.x, v1 = acc[ms][ns][1] + b2.y;
            float v2 = acc[ms][ns][2] + b2.x, v3 = acc[ms][ns][3] + b2.y;
            if (act) { v0 = leaky_f(v0); v1 = leaky_f(v1); v2 = leaky_f(v2); v3 = leaky_f(v3); }
            if (r1 < NN) *(float2*)&g_hval[(size_t)r1 * HH + col] = make_float2(v0, v1);
            if (r2 < NN) *(float2*)&g_hval[(size_t)r2 * HH + col] = make_float2(v2, v3);
        }
    }
}

// ---------------- attention scores ----------------
__global__ void k_scores1(const float* __restrict__ asrc, const float* __restrict__ adst) {
    int w = (blockIdx.x * blockDim.x + threadIdx.x) >> 5;
    int lane = threadIdx.x & 31;
    if (w >= NN) return;
    float a = 0.f, b = 0.f;
    #pragma unroll
    for (int q = 0; q < 4; q++) {
        int f = lane + q * 32;
        float hv = g_h[w * HH + f];
        a += hv * asrc[f];
        b += hv * adst[f];
    }
    #pragma unroll
    for (int o = 16; o; o >>= 1) {
        a += __shfl_xor_sync(0xffffffffu, a, o);
        b += __shfl_xor_sync(0xffffffffu, b, o);
    }
    if (lane == 0) { g_ssrc[w] = a; g_sdst[w] = b; }
}

__global__ void k_scores4(const float* __restrict__ asrc, const float* __restrict__ adst) {
    int w = (blockIdx.x * blockDim.x + threadIdx.x) >> 5;
    int lane = threadIdx.x & 31;
    if (w >= NN) return;
    float as[4] = {0, 0, 0, 0}, ad[4] = {0, 0, 0, 0};
    #pragma unroll
    for (int q = 0; q < 4; q++) {
        int f = lane + q * 32;
        float hv = g_h[w * HH + f];
        #pragma unroll
        for (int h = 0; h < 4; h++) {
            as[h] += hv * asrc[h * HH + f];
            ad[h] += hv * adst[h * HH + f];
        }
    }
    #pragma unroll
    for (int h = 0; h < 4; h++) {
        #pragma unroll
        for (int o = 16; o; o >>= 1) {
            as[h] += __shfl_xor_sync(0xffffffffu, as[h], o);
            ad[h] += __shfl_xor_sync(0xffffffffu, ad[h], o);
        }
    }
    if (lane == 0) {
        #pragma unroll
        for (int h = 0; h < 4; h++) { g_ssrc[w * 4 + h] = as[h]; g_sdst[w * 4 + h] = ad[h]; }
    }
}

// ---------------- attention aggregate + BN + residual + leaky (in-place on g_h) ----------------
__global__ void __launch_bounds__(256) k_attn(const float* __restrict__ bn_g,
                                              const float* __restrict__ bn_b,
                                              const float* __restrict__ bn_m,
                                              const float* __restrict__ bn_v,
                                              int residual, int multi) {
    int w = (blockIdx.x * blockDim.x + threadIdx.x) >> 5;
    int lane = threadIdx.x & 31;
    if (w >= NN) return;
    int s0 = g_rowptr[w], e0 = g_rowptr[w + 1];
    int hd = multi ? (lane >> 3) : 0;
    float si = multi ? g_ssrc[w * 4 + hd] : g_ssrc[w];

    int f0 = lane * 4;
    float4 bnm4 = *(const float4*)&bn_m[f0];
    float4 bnv4 = *(const float4*)&bn_v[f0];
    float4 bng4 = *(const float4*)&bn_g[f0];
    float4 bnb4 = *(const float4*)&bn_b[f0];
    float sc0 = bng4.x * rsqrtf(bnv4.x + BN_EPS);
    float sc1 = bng4.y * rsqrtf(bnv4.y + BN_EPS);
    float sc2 = bng4.z * rsqrtf(bnv4.z + BN_EPS);
    float sc3 = bng4.w * rsqrtf(bnv4.w + BN_EPS);

    float4 acc = make_float4(0, 0, 0, 0);
    float m = -CUDART_INF_F, s = 0.f;
    const float4* hv4 = (const float4*)g_hval;
    for (int j = s0; j < e0; j++) {
        int c = __ldg(&g_cols[j]);
        float sd = multi ? __ldg(&g_sdst[c * 4 + hd]) : __ldg(&g_sdst[c]);
        float e = leaky_f(si + sd);
        float wgt;
        if (e <= m) {
            wgt = __expf(e - m);
        } else {
            float sc = __expf(m - e);   // exp(-inf)=0 on first edge
            s *= sc;
            acc.x *= sc; acc.y *= sc; acc.z *= sc; acc.w *= sc;
            m = e;
            wgt = 1.f;
        }
        s += wgt;
        float4 hv = __ldg(&hv4[c * 32 + lane]);
        acc.x += wgt * hv.x; acc.y += wgt * hv.y;
        acc.z += wgt * hv.z; acc.w += wgt * hv.w;
    }
    float inv = 1.f / (s + 1e-16f);
    float o0 = (acc.x * inv - bnm4.x) * sc0 + bnb4.x;
    float o1 = (acc.y * inv - bnm4.y) * sc1 + bnb4.y;
    float o2 = (acc.z * inv - bnm4.z) * sc2 + bnb4.z;
    float o3 = (acc.w * inv - bnm4.w) * sc3 + bnb4.w;
    if (residual) {
        float4 r4 = *(const float4*)&g_h[w * HH + f0];
        o0 += r4.x; o1 += r4.y; o2 += r4.z; o3 += r4.w;
    }
    *(float4*)&g_h[w * HH + f0] =
        make_float4(leaky_f(o0), leaky_f(o1), leaky_f(o2), leaky_f(o3));
}

// ---------------- output head: out = x[:,15:18] + (g_hval @ W_o2 + b_o2) ----------------
__global__ void k_out(const float* __restrict__ x, const float* __restrict__ Wo2,
                      const float* __restrict__ bo2, float* __restrict__ out) {
    int w = (blockIdx.x * blockDim.x + threadIdx.x) >> 5;
    int lane = threadIdx.x & 31;
    if (w >= NN) return;
    float a0 = 0.f, a1 = 0.f, a2 = 0.f;
    #pragma unroll
    for (int q = 0; q < 4; q++) {
        int f = lane + q * 32;
        float t = g_hval[w * HH + f];
        a0 += t * Wo2[f * 3 + 0];
        a1 += t * Wo2[f * 3 + 1];
        a2 += t * Wo2[f * 3 + 2];
    }
    #pragma unroll
    for (int o = 16; o; o >>= 1) {
        a0 += __shfl_xor_sync(0xffffffffu, a0, o);
        a1 += __shfl_xor_sync(0xffffffffu, a1, o);
        a2 += __shfl_xor_sync(0xffffffffu, a2, o);
    }
    if (lane < 3) {
        float a = (lane == 0) ? a0 : (lane == 1) ? a1 : a2;
        out[w * 3 + lane] = x[w * DIN + 15 + lane] + a + bo2[lane];
    }
}

// ---------------- launch ----------------
extern "C" void kernel_launch(void* const* d_in, const int* in_sizes, int n_in,
                              void* d_out, int out_size) {
    const float* x     = (const float*)d_in[0];
    const int*   ei    = (const int*)d_in[1];
    const float* Win   = (const float*)d_in[2];
    const float* bin   = (const float*)d_in[3];
    const float* Wagg  = (const float*)d_in[4];
    const float* bagg  = (const float*)d_in[5];
    const float* shWv  = (const float*)d_in[6];
    const float* shb   = (const float*)d_in[7];
    const float* shas  = (const float*)d_in[8];
    const float* shad  = (const float*)d_in[9];
    const float* mhWv  = (const float*)d_in[10];
    const float* mhb   = (const float*)d_in[11];
    const float* mhas  = (const float*)d_in[12];
    const float* mhad  = (const float*)d_in[13];
    const float* bng   = (const float*)d_in[14];
    const float* bnb   = (const float*)d_in[15];
    const float* bnm   = (const float*)d_in[16];
    const float* bnv   = (const float*)d_in[17];
    const float* Wo1   = (const float*)d_in[18];
    const float* bo1   = (const float*)d_in[19];
    const float* Wo2   = (const float*)d_in[20];
    const float* bo2   = (const float*)d_in[21];
    float* out = (float*)d_out;

    cudaFuncSetAttribute(k_gemm_mma, cudaFuncAttributeMaxDynamicSharedMemorySize, GM_SM_TOTAL);

    const int WPB = 8;
    dim3 nwarp_grid((NN + WPB - 1) / WPB);
    dim3 mma_grid((NN + 127) / 128);

    // CSR build + weight conversion
    k_zero<<<(NN + 255) / 256, 256>>>();
    k_count<<<(EE + 255) / 256, 256>>>(ei);
    k_scan<<<1, 1024>>>();
    k_scatter<<<(EE + 255) / 256, 256>>>(ei);
    k_wt<<<(4 * HH * HH + 255) / 256, 256>>>(shWv, mhWv, Wo1);

    // input transform
    k_nmean<<<nwarp_grid, WPB * 32>>>(x);
    k_input<<<(NN + 31) / 32, 128>>>(x, Win, bin, Wagg, bagg);

    // layer 0: single-head, BN[0], residual
    k_gemm_mma<<<mma_grid, 256, GM_SM_TOTAL>>>(0, shb, 0);
    k_scores1<<<nwarp_grid, WPB * 32>>>(shas, shad);
    k_attn<<<nwarp_grid, WPB * 32>>>(bng, bnb, bnm, bnv, 1, 0);

    // layer 1: multi-head, BN[1], no residual
    k_gemm_mma<<<mma_grid, 256, GM_SM_TOTAL>>>(1, mhb, 0);
    k_scores4<<<nwarp_grid, WPB * 32>>>(mhas, mhad);
    k_attn<<<nwarp_grid, WPB * 32>>>(bng + HH, bnb + HH, bnm + HH, bnv + HH, 0, 1);

    // layer 2: single-head (set 1), BN[2], residual
    k_gemm_mma<<<mma_grid, 256, GM_SM_TOTAL>>>(2, shb + HH, 0);
    k_scores1<<<nwarp_grid, WPB * 32>>>(shas + HH, shad + HH);
    k_attn<<<nwarp_grid, WPB * 32>>>(bng + 2 * HH, bnb + 2 * HH, bnm + 2 * HH, bnv + 2 * HH, 1, 0);

    // output head
    k_gemm_mma<<<mma_grid, 256, GM_SM_TOTAL>>>(3, bo1, 1);
    k_out<<<nwarp_grid, WPB * 32>>>(x, Wo2, bo2, out);
}

// round 10
// speedup vs baseline: 1.5324x; 1.2214x over previous
#include <cuda_runtime.h>
#include <cuda_bf16.h>
#include <math_constants.h>
#include <cstdint>

#define NN 50000
#define EE 800000
#define DIN 18
#define HH 128
#define NEG_SLOPE 0.2f
#define BN_EPS 1e-5f

// ---------------- scratch (no allocation allowed) ----------------
__device__ int   g_deg[NN];
__device__ int   g_fill[NN];
__device__ int   g_rowptr[NN + 1];
__device__ int   g_cols[EE];
__device__ float g_nmean[NN * DIN];
__device__ float g_h[NN * HH];
__device__ __nv_bfloat16 g_hvalb[NN * HH];     // bf16 attention values
__device__ float g_ssrc[2][NN * 4];            // ping-pong score buffers
__device__ float g_sdst[2][NN * 4];
__device__ __nv_bfloat16 g_wtb[4][HH * HH];    // bf16 weights, [N][K] (col-major B)

__device__ __forceinline__ float leaky_f(float v) { return v >= 0.f ? v : NEG_SLOPE * v; }

// ---------------- CSR build ----------------
__global__ void k_zero() {
    int i = blockIdx.x * blockDim.x + threadIdx.x;
    if (i < NN) { g_deg[i] = 0; g_fill[i] = 0; }
}

__global__ void k_count(const int* __restrict__ ei) {
    int e = blockIdx.x * blockDim.x + threadIdx.x;
    if (e < EE) atomicAdd(&g_deg[ei[e]], 1);
}

__global__ void k_scan() {
    __shared__ int wsum[32];
    __shared__ int carry;
    int tid = threadIdx.x;
    int lane = tid & 31, wid = tid >> 5;
    if (tid == 0) { carry = 0; g_rowptr[0] = 0; }
    __syncthreads();
    for (int base = 0; base < NN; base += 1024) {
        int idx = base + tid;
        int v = (idx < NN) ? g_deg[idx] : 0;
        int x = v;
        #pragma unroll
        for (int o = 1; o < 32; o <<= 1) {
            int y = __shfl_up_sync(0xffffffffu, x, o);
            if (lane >= o) x += y;
        }
        if (lane == 31) wsum[wid] = x;
        __syncthreads();
        if (wid == 0) {
            int s = wsum[lane];
            #pragma unroll
            for (int o = 1; o < 32; o <<= 1) {
                int y = __shfl_up_sync(0xffffffffu, s, o);
                if (lane >= o) s += y;
            }
            wsum[lane] = s;
        }
        __syncthreads();
        int incl = x + (wid ? wsum[wid - 1] : 0) + carry;
        if (idx < NN) g_rowptr[idx + 1] = incl;
        __syncthreads();
        if (tid == 1023) carry = incl;
        __syncthreads();
    }
}

__global__ void k_scatter(const int* __restrict__ ei) {
    int e = blockIdx.x * blockDim.x + threadIdx.x;
    if (e < EE) {
        int r = ei[e];
        int pos = g_rowptr[r] + atomicAdd(&g_fill[r], 1);
        g_cols[pos] = ei[EE + e];
    }
}

// ---------------- neighbor mean (warp per node) ----------------
__global__ void k_nmean(const float* __restrict__ x) {
    int w = (blockIdx.x * blockDim.x + threadIdx.x) >> 5;
    int lane = threadIdx.x & 31;
    if (w >= NN) return;
    int s0 = g_rowptr[w], e0 = g_rowptr[w + 1];
    float acc = 0.f;
    for (int j = s0; j < e0; j++) {
        int c = __ldg(&g_cols[j]);
        if (lane < DIN) acc += __ldg(&x[c * DIN + lane]);
    }
    float inv = 1.f / ((float)(e0 - s0) + 1e-8f);
    if (lane < DIN) g_nmean[w * DIN + lane] = acc * inv;
}

// ---------------- input transform ----------------
__global__ void k_input(const float* __restrict__ x, const float* __restrict__ Win,
                        const float* __restrict__ bin, const float* __restrict__ Wagg,
                        const float* __restrict__ bagg) {
    __shared__ float xs[32][DIN];
    __shared__ float ns[32][DIN];
    int f = threadIdx.x;   // 128
    int n0 = blockIdx.x * 32;
    for (int t = f; t < 32 * DIN; t += 128) {
        int m = t / DIN, k = t % DIN;
        int gn = n0 + m;
        xs[m][k] = (gn < NN) ? x[gn * DIN + k] : 0.f;
        ns[m][k] = (gn < NN) ? g_nmean[gn * DIN + k] : 0.f;
    }
    float wi[DIN], wa[DIN];
    #pragma unroll
    for (int k = 0; k < DIN; k++) { wi[k] = Win[k * HH + f]; wa[k] = Wagg[k * HH + f]; }
    float bias = bin[f] + bagg[f];
    __syncthreads();
    for (int m = 0; m < 32; m++) {
        int gn = n0 + m;
        if (gn >= NN) break;
        float acc = bias;
        #pragma unroll
        for (int k = 0; k < DIN; k++) acc += xs[m][k] * wi[k] + ns[m][k] * wa[k];
        g_h[gn * HH + f] = acc;
    }
}

// ---------------- weight pre-pass: bf16, transposed to [N][K] ----------------
__global__ void k_wt(const float* __restrict__ shWv, const float* __restrict__ mhWv,
                     const float* __restrict__ Wo1) {
    int t = blockIdx.x * blockDim.x + threadIdx.x;     // 4 * 16384
    int buf = t >> 14;
    int r = t & 16383;
    int n = r >> 7, k = r & 127;
    float v;
    if (buf == 1) {
        int h = n >> 5, e = n & 31;
        v = mhWv[(h * HH + k) * 32 + e];
    } else if (buf == 0) {
        v = shWv[k * HH + n];
    } else if (buf == 2) {
        v = shWv[HH * HH + k * HH + n];
    } else {
        v = Wo1[k * HH + n];
    }
    g_wtb[buf][n * HH + k] = __float2bfloat16(v);
}

// ---------------- mma.sync GEMM: g_hvalb = bf16(g_h @ W + bias [leaky]) ----------------
#define GM_STRIDE 136
#define GM_SM_B 34816
#define GM_SM_TOTAL 69632

#define MMA16816(c, a, b) \
    asm volatile("mma.sync.aligned.m16n8k16.row.col.f32.bf16.bf16.f32 " \
        "{%0,%1,%2,%3}, {%4,%5,%6,%7}, {%8,%9}, {%0,%1,%2,%3};" \
        : "+f"((c)[0]), "+f"((c)[1]), "+f"((c)[2]), "+f"((c)[3]) \
        : "r"((a)[0]), "r"((a)[1]), "r"((a)[2]), "r"((a)[3]), \
          "r"((b)[0]), "r"((b)[1]))

__global__ void __launch_bounds__(256) k_gemm_mma(int widx, const float* __restrict__ bias,
                                                  int act) {
    extern __shared__ __align__(16) char smem[];
    __nv_bfloat16* As = (__nv_bfloat16*)smem;
    __nv_bfloat16* Bs = (__nv_bfloat16*)(smem + GM_SM_B);
    int tid = threadIdx.x, lane = tid & 31, wid = tid >> 5;
    int row0 = blockIdx.x * 128;

    // ---- convert A rows fp32 -> bf16 ----
    {
        int r = tid >> 1, half = tid & 1;
        int gr = row0 + r;
        const float4* src = (const float4*)&g_h[(size_t)gr * HH + half * 64];
        __nv_bfloat16* dst = &As[r * GM_STRIDE + half * 64];
        #pragma unroll
        for (int q = 0; q < 8; q++) {
            float4 f0, f1;
            if (gr < NN) { f0 = src[q * 2]; f1 = src[q * 2 + 1]; }
            else { f0 = make_float4(0, 0, 0, 0); f1 = f0; }
            __nv_bfloat162 h0 = __floats2bfloat162_rn(f0.x, f0.y);
            __nv_bfloat162 h1 = __floats2bfloat162_rn(f0.z, f0.w);
            __nv_bfloat162 h2 = __floats2bfloat162_rn(f1.x, f1.y);
            __nv_bfloat162 h3 = __floats2bfloat162_rn(f1.z, f1.w);
            uint4 v;
            v.x = *(uint32_t*)&h0; v.y = *(uint32_t*)&h1;
            v.z = *(uint32_t*)&h2; v.w = *(uint32_t*)&h3;
            *(uint4*)(dst + q * 8) = v;
        }
    }
    // ---- copy Wt bf16 gmem -> smem ----
    {
        const uint4* src = (const uint4*)g_wtb[widx];
        #pragma unroll
        for (int i = 0; i < 8; i++) {
            int idx = tid + i * 256;
            int n = idx >> 4, j = idx & 15;
            *(uint4*)&Bs[n * GM_STRIDE + j * 8] = src[n * 16 + j];
        }
    }
    __syncthreads();

    int mw = wid & 1, nw = wid >> 1;
    int m0 = mw * 64, n0 = nw * 32;
    int gid = lane >> 2, qd = (lane & 3) * 2;

    float acc[4][4][4];
    #pragma unroll
    for (int a = 0; a < 4; a++)
        #pragma unroll
        for (int b = 0; b < 4; b++)
            #pragma unroll
            for (int c = 0; c < 4; c++) acc[a][b][c] = 0.f;

    #pragma unroll
    for (int ks = 0; ks < 8; ks++) {
        int kc = ks * 16 + qd;
        uint32_t af[4][4], bf[4][2];
        #pragma unroll
        for (int ms = 0; ms < 4; ms++) {
            const __nv_bfloat16* p = &As[(m0 + ms * 16 + gid) * GM_STRIDE + kc];
            af[ms][0] = *(const uint32_t*)p;
            af[ms][1] = *(const uint32_t*)(p + 8 * GM_STRIDE);
            af[ms][2] = *(const uint32_t*)(p + 8);
            af[ms][3] = *(const uint32_t*)(p + 8 * GM_STRIDE + 8);
        }
        #pragma unroll
        for (int ns = 0; ns < 4; ns++) {
            const __nv_bfloat16* p = &Bs[(n0 + ns * 8 + gid) * GM_STRIDE + kc];
            bf[ns][0] = *(const uint32_t*)p;
            bf[ns][1] = *(const uint32_t*)(p + 8);
        }
        #pragma unroll
        for (int ms = 0; ms < 4; ms++)
            #pragma unroll
            for (int ns = 0; ns < 4; ns++)
                MMA16816(acc[ms][ns], af[ms], bf[ns]);
    }

    // ---- epilogue: bias (+leaky), bf16 stores ----
    #pragma unroll
    for (int ms = 0; ms < 4; ms++) {
        int r1 = row0 + m0 + ms * 16 + gid;
        int r2 = r1 + 8;
        #pragma unroll
        for (int ns = 0; ns < 4; ns++) {
            int col = n0 + ns * 8 + qd;
            float2 b2 = *(const float2*)&bias[col];
            float v0 = acc[ms][ns][0] + b2.x, v1 = acc[ms][ns][1] + b2.y;
            float v2 = acc[ms][ns][2] + b2.x, v3 = acc[ms][ns][3] + b2.y;
            if (act) { v0 = leaky_f(v0); v1 = leaky_f(v1); v2 = leaky_f(v2); v3 = leaky_f(v3); }
            if (r1 < NN) *(__nv_bfloat162*)&g_hvalb[(size_t)r1 * HH + col] = __floats2bfloat162_rn(v0, v1);
            if (r2 < NN) *(__nv_bfloat162*)&g_hvalb[(size_t)r2 * HH + col] = __floats2bfloat162_rn(v2, v3);
        }
    }
}

// ---------------- layer-0 scores (h from k_input) -> buffer 0 ----------------
__global__ void k_scores1(const float* __restrict__ asrc, const float* __restrict__ adst) {
    int w = (blockIdx.x * blockDim.x + threadIdx.x) >> 5;
    int lane = threadIdx.x & 31;
    if (w >= NN) return;
    float a = 0.f, b = 0.f;
    #pragma unroll
    for (int q = 0; q < 4; q++) {
        int f = lane + q * 32;
        float hv = g_h[w * HH + f];
        a += hv * asrc[f];
        b += hv * adst[f];
    }
    #pragma unroll
    for (int o = 16; o; o >>= 1) {
        a += __shfl_xor_sync(0xffffffffu, a, o);
        b += __shfl_xor_sync(0xffffffffu, b, o);
    }
    if (lane == 0) { g_ssrc[0][w] = a; g_sdst[0][w] = b; }
}

// ---------------- attention + BN + residual + leaky + NEXT-layer scores ----------------
// Reads scores from buffer rb, writes next-layer scores (nxt_heads in {0,1,4}) to rb^1.
__global__ void __launch_bounds__(256) k_attn(const float* __restrict__ bn_g,
                                              const float* __restrict__ bn_b,
                                              const float* __restrict__ bn_m,
                                              const float* __restrict__ bn_v,
                                              int residual, int multi, int rb,
                                              const float* __restrict__ nxt_asrc,
                                              const float* __restrict__ nxt_adst,
                                              int nxt_heads) {
    int w = (blockIdx.x * blockDim.x + threadIdx.x) >> 5;
    int lane = threadIdx.x & 31;
    if (w >= NN) return;
    int s0 = g_rowptr[w], e0 = g_rowptr[w + 1];
    int hd = multi ? (lane >> 3) : 0;
    const float* srcb = g_ssrc[rb];
    const float* dstb = g_sdst[rb];
    float si = multi ? srcb[w * 4 + hd] : srcb[w];

    int f0 = lane * 4;
    float4 bnm4 = *(const float4*)&bn_m[f0];
    float4 bnv4 = *(const float4*)&bn_v[f0];
    float4 bng4 = *(const float4*)&bn_g[f0];
    float4 bnb4 = *(const float4*)&bn_b[f0];
    float sc0 = bng4.x * rsqrtf(bnv4.x + BN_EPS);
    float sc1 = bng4.y * rsqrtf(bnv4.y + BN_EPS);
    float sc2 = bng4.z * rsqrtf(bnv4.z + BN_EPS);
    float sc3 = bng4.w * rsqrtf(bnv4.w + BN_EPS);

    float a0 = 0.f, a1 = 0.f, a2 = 0.f, a3 = 0.f, s = 0.f;
    const uint2* hb = (const uint2*)g_hvalb;
    for (int j = s0; j < e0; j++) {
        int c = __ldg(&g_cols[j]);
        float sd = multi ? __ldg(&dstb[c * 4 + hd]) : __ldg(&dstb[c]);
        float wgt = __expf(leaky_f(si + sd));
        uint2 hv = __ldg(&hb[(size_t)c * 32 + lane]);
        float2 fa = __bfloat1622float2(*(const __nv_bfloat162*)&hv.x);
        float2 fb = __bfloat1622float2(*(const __nv_bfloat162*)&hv.y);
        s += wgt;
        a0 += wgt * fa.x; a1 += wgt * fa.y;
        a2 += wgt * fb.x; a3 += wgt * fb.y;
    }
    float inv = 1.f / (s + 1e-16f);
    float o0 = (a0 * inv - bnm4.x) * sc0 + bnb4.x;
    float o1 = (a1 * inv - bnm4.y) * sc1 + bnb4.y;
    float o2 = (a2 * inv - bnm4.z) * sc2 + bnb4.z;
    float o3 = (a3 * inv - bnm4.w) * sc3 + bnb4.w;
    if (residual) {
        float4 r4 = *(const float4*)&g_h[w * HH + f0];
        o0 += r4.x; o1 += r4.y; o2 += r4.z; o3 += r4.w;
    }
    o0 = leaky_f(o0); o1 = leaky_f(o1); o2 = leaky_f(o2); o3 = leaky_f(o3);
    *(float4*)&g_h[w * HH + f0] = make_float4(o0, o1, o2, o3);

    // ---- fused next-layer scores from in-register h (write rb^1) ----
    if (nxt_heads == 1) {
        float4 av = *(const float4*)&nxt_asrc[f0];
        float4 dv = *(const float4*)&nxt_adst[f0];
        float pa = o0 * av.x + o1 * av.y + o2 * av.z + o3 * av.w;
        float pb = o0 * dv.x + o1 * dv.y + o2 * dv.z + o3 * dv.w;
        #pragma unroll
        for (int o = 16; o; o >>= 1) {
            pa += __shfl_xor_sync(0xffffffffu, pa, o);
            pb += __shfl_xor_sync(0xffffffffu, pb, o);
        }
        if (lane == 0) { g_ssrc[rb ^ 1][w] = pa; g_sdst[rb ^ 1][w] = pb; }
    } else if (nxt_heads == 4) {
        #pragma unroll
        for (int hh = 0; hh < 4; hh++) {
            float4 av = *(const float4*)&nxt_asrc[hh * HH + f0];
            float4 dv = *(const float4*)&nxt_adst[hh * HH + f0];
            float pa = o0 * av.x + o1 * av.y + o2 * av.z + o3 * av.w;
            float pb = o0 * dv.x + o1 * dv.y + o2 * dv.z + o3 * dv.w;
            #pragma unroll
            for (int o = 16; o; o >>= 1) {
                pa += __shfl_xor_sync(0xffffffffu, pa, o);
                pb += __shfl_xor_sync(0xffffffffu, pb, o);
            }
            if (lane == 0) { g_ssrc[rb ^ 1][w * 4 + hh] = pa; g_sdst[rb ^ 1][w * 4 + hh] = pb; }
        }
    }
}

// ---------------- output head: out = x[:,15:18] + (hval @ W_o2 + b_o2) ----------------
__global__ void k_out(const float* __restrict__ x, const float* __restrict__ Wo2,
                      const float* __restrict__ bo2, float* __restrict__ out) {
    int w = (blockIdx.x * blockDim.x + threadIdx.x) >> 5;
    int lane = threadIdx.x & 31;
    if (w >= NN) return;
    float a0 = 0.f, a1 = 0.f, a2 = 0.f;
    #pragma unroll
    for (int q = 0; q < 4; q++) {
        int f = lane + q * 32;
        float t = __bfloat162float(g_hvalb[(size_t)w * HH + f]);
        a0 += t * Wo2[f * 3 + 0];
        a1 += t * Wo2[f * 3 + 1];
        a2 += t * Wo2[f * 3 + 2];
    }
    #pragma unroll
    for (int o = 16; o; o >>= 1) {
        a0 += __shfl_xor_sync(0xffffffffu, a0, o);
        a1 += __shfl_xor_sync(0xffffffffu, a1, o);
        a2 += __shfl_xor_sync(0xffffffffu, a2, o);
    }
    if (lane < 3) {
        float a = (lane == 0) ? a0 : (lane == 1) ? a1 : a2;
        out[w * 3 + lane] = x[w * DIN + 15 + lane] + a + bo2[lane];
    }
}

// ---------------- launch ----------------
extern "C" void kernel_launch(void* const* d_in, const int* in_sizes, int n_in,
                              void* d_out, int out_size) {
    const float* x     = (const float*)d_in[0];
    const int*   ei    = (const int*)d_in[1];
    const float* Win   = (const float*)d_in[2];
    const float* bin   = (const float*)d_in[3];
    const float* Wagg  = (const float*)d_in[4];
    const float* bagg  = (const float*)d_in[5];
    const float* shWv  = (const float*)d_in[6];
    const float* shb   = (const float*)d_in[7];
    const float* shas  = (const float*)d_in[8];
    const float* shad  = (const float*)d_in[9];
    const float* mhWv  = (const float*)d_in[10];
    const float* mhb   = (const float*)d_in[11];
    const float* mhas  = (const float*)d_in[12];
    const float* mhad  = (const float*)d_in[13];
    const float* bng   = (const float*)d_in[14];
    const float* bnb   = (const float*)d_in[15];
    const float* bnm   = (const float*)d_in[16];
    const float* bnv   = (const float*)d_in[17];
    const float* Wo1   = (const float*)d_in[18];
    const float* bo1   = (const float*)d_in[19];
    const float* Wo2   = (const float*)d_in[20];
    const float* bo2   = (const float*)d_in[21];
    float* out = (float*)d_out;

    cudaFuncSetAttribute(k_gemm_mma, cudaFuncAttributeMaxDynamicSharedMemorySize, GM_SM_TOTAL);

    const int WPB = 8;
    dim3 nwarp_grid((NN + WPB - 1) / WPB);
    dim3 mma_grid((NN + 127) / 128);

    // CSR build + weight conversion
    k_zero<<<(NN + 255) / 256, 256>>>();
    k_count<<<(EE + 255) / 256, 256>>>(ei);
    k_scan<<<1, 1024>>>();
    k_scatter<<<(EE + 255) / 256, 256>>>(ei);
    k_wt<<<(4 * HH * HH + 255) / 256, 256>>>(shWv, mhWv, Wo1);

    // input transform + layer-0 scores (buffer 0)
    k_nmean<<<nwarp_grid, WPB * 32>>>(x);
    k_input<<<(NN + 31) / 32, 128>>>(x, Win, bin, Wagg, bagg);
    k_scores1<<<nwarp_grid, WPB * 32>>>(shas, shad);

    // layer 0: single-head, BN[0], residual; reads buf0, emits 4-head scores -> buf1
    k_gemm_mma<<<mma_grid, 256, GM_SM_TOTAL>>>(0, shb, 0);
    k_attn<<<nwarp_grid, WPB * 32>>>(bng, bnb, bnm, bnv, 1, 0, 0, mhas, mhad, 4);

    // layer 1: multi-head, BN[1], no residual; reads buf1, emits layer-2 scores -> buf0
    k_gemm_mma<<<mma_grid, 256, GM_SM_TOTAL>>>(1, mhb, 0);
    k_attn<<<nwarp_grid, WPB * 32>>>(bng + HH, bnb + HH, bnm + HH, bnv + HH, 0, 1, 1,
                                     shas + HH, shad + HH, 1);

    // layer 2: single-head (set 1), BN[2], residual; reads buf0, no next scores
    k_gemm_mma<<<mma_grid, 256, GM_SM_TOTAL>>>(2, shb + HH, 0);
    k_attn<<<nwarp_grid, WPB * 32>>>(bng + 2 * HH, bnb + 2 * HH, bnm + 2 * HH, bnv + 2 * HH,
                                     1, 0, 0, nullptr, nullptr, 0);

    // output head
    k_gemm_mma<<<mma_grid, 256, GM_SM_TOTAL>>>(3, bo1, 1);
    k_out<<<nwarp_grid, WPB * 32>>>(x, Wo2, bo2, out);
}